// round 11
// baseline (speedup 1.0000x reference)
#include <cuda_runtime.h>
#include <cuda_fp16.h>
#include <mma.h>
#include <cstdint>

using namespace nvcuda;

#define NNODES 50000
#define NEDGES 400000
#define DDIM   512
#define NCAT   1024
#define NEG_SLOPE 0.01f
#define FILL 2.0f

// ---------------------------------------------------------------------------
// Device scratch (static: no allocations allowed)
// ---------------------------------------------------------------------------
__device__ __half g_Xh[(size_t)3 * NNODES * DDIM];  // fp16 inputs (153.6MB)
__device__ __half g_Bh[(size_t)DDIM * NCAT];        // fp16 [W | Wres] (1MB)
__device__ __half g_Hh[(size_t)3 * NNODES * DDIM];  // H_t = X_t @ W (fp16)
__device__ float  g_deg[NNODES];
__device__ float  g_dis[NNODES];
__device__ int    g_cnt[NNODES];
__device__ int    g_off[NNODES + 1];
__device__ int    g_bsum[128];
__device__ int    g_srcs[NEDGES];
__device__ float  g_coef[NEDGES];

struct alignas(8) half4 { __half2 a, b; };

// ---------------------------------------------------------------------------
// fp32 -> fp16 conversion passes
// ---------------------------------------------------------------------------
__global__ void conv_x_kernel(const float* __restrict__ x0,
                              const float* __restrict__ x1,
                              const float* __restrict__ x2, int n4) {
    int i = blockIdx.x * blockDim.x + threadIdx.x;
    if (i >= n4) return;
    int t = blockIdx.y;
    const float* x = (t == 0) ? x0 : (t == 1) ? x1 : x2;
    float4 v = ((const float4*)x)[i];
    half4 o;
    o.a = __floats2half2_rn(v.x, v.y);
    o.b = __floats2half2_rn(v.z, v.w);
    ((half4*)(g_Xh + (size_t)t * NNODES * DDIM))[i] = o;
}

__global__ void conv_b_kernel(const float* __restrict__ W, const float* __restrict__ Wres) {
    int i = blockIdx.x * blockDim.x + threadIdx.x;
    if (i >= DDIM * NCAT) return;
    int k = i >> 10, n = i & 1023;
    float v = (n < DDIM) ? W[(size_t)k * DDIM + n] : Wres[(size_t)k * DDIM + (n - DDIM)];
    g_Bh[i] = __float2half_rn(v);
}

// ---------------------------------------------------------------------------
// Degree / norm / CSR build
// ---------------------------------------------------------------------------
__global__ void init_kernel() {
    int n = blockIdx.x * blockDim.x + threadIdx.x;
    if (n < NNODES) { g_deg[n] = FILL; g_cnt[n] = 0; }
}
__global__ void accum_kernel(const int* __restrict__ dst, const float* __restrict__ w) {
    int e = blockIdx.x * blockDim.x + threadIdx.x;
    if (e < NEDGES) {
        int d = dst[e];
        atomicAdd(&g_deg[d], w[e]);
        atomicAdd(&g_cnt[d], 1);
    }
}
__global__ void calc_dis_kernel() {
    int n = blockIdx.x * blockDim.x + threadIdx.x;
    if (n < NNODES) {
        float d = g_deg[n];
        g_dis[n] = (d > 0.0f) ? rsqrtf(d) : 0.0f;
    }
}

#define SCAN_BS 512
#define SCAN_NB ((NNODES + SCAN_BS - 1) / SCAN_BS)   // 98

__global__ void scan1_kernel() {
    __shared__ int s[SCAN_BS];
    int tid = threadIdx.x;
    int i = blockIdx.x * SCAN_BS + tid;
    int val = (i < NNODES) ? g_cnt[i] : 0;
    s[tid] = val;
    __syncthreads();
    #pragma unroll
    for (int o = 1; o < SCAN_BS; o <<= 1) {
        int t = (tid >= o) ? s[tid - o] : 0;
        __syncthreads();
        s[tid] += t;
        __syncthreads();
    }
    int incl = s[tid];
    if (i < NNODES) g_off[i] = incl - val;
    if (tid == SCAN_BS - 1) g_bsum[blockIdx.x] = incl;
}
__global__ void scan2_kernel() {
    if (threadIdx.x == 0) {
        int run = 0;
        for (int b = 0; b < SCAN_NB; b++) { int t = g_bsum[b]; g_bsum[b] = run; run += t; }
    }
}
__global__ void scan3_kernel() {
    int i = blockIdx.x * blockDim.x + threadIdx.x;
    if (i < NNODES) { g_off[i] += g_bsum[i >> 9]; g_cnt[i] = 0; }
    if (i == 0) g_off[NNODES] = NEDGES;
}
__global__ void fill_kernel(const int* __restrict__ src, const int* __restrict__ dst,
                            const float* __restrict__ w) {
    int e = blockIdx.x * blockDim.x + threadIdx.x;
    if (e >= NEDGES) return;
    int s = src[e], d = dst[e];
    int pos = atomicAdd(&g_cnt[d], 1);
    int slot = g_off[d] + pos;
    g_srcs[slot] = s;
    g_coef[slot] = g_dis[s] * w[e] * g_dis[d];
}

// ---------------------------------------------------------------------------
// FP16 WMMA GEMM (fp32 accumulate), batched over the 3 inputs via grid.z.
// C_t[M, 1024] = Xh_t[M,512] @ g_Bh.
// CTA tile 128x256, 8 warps in a 2x4 grid, warp tile 64x64 (4x4 wmma).
// 3-stage cp.async pipeline, one __syncthreads per K-chunk.
// H tiles (cols<512) -> fp16 via two-half smem staging; O tiles -> fp32.
// ---------------------------------------------------------------------------
#define MT 128
#define NT 256
#define BK 32
#define LDA (BK + 8)        // halves
#define LDB (NT + 8)        // halves (264 -> 528B rows, 16B aligned)
#define A_STAGE (MT * LDA)  // 5120 halves
#define B_STAGE (BK * LDB)  // 8448 halves
#define STAGES 3
#define SMEM_BYTES 83968    // >= 3*(A_STAGE+B_STAGE)*2 = 81408, >= 64KB staging
#define CHUNKS (DDIM / BK)  // 16

__global__ __launch_bounds__(256) void gemm_fp16_wmma_kernel(
    float* __restrict__ Obase,       // [3, M, 512] (d_out)
    int M)
{
    extern __shared__ char smem_raw[];
    __half* As = (__half*)smem_raw;
    __half* Bs = As + STAGES * A_STAGE;

    const int tid = threadIdx.x;
    const int wid = tid >> 5;
    const int m0 = blockIdx.y * MT;
    const int ncol0 = blockIdx.x * NT;        // 0, 256, 512, 768
    const int t = blockIdx.z;

    const __half* A = g_Xh + (size_t)t * M * DDIM;
    const size_t slice = (size_t)M * DDIM;

    const int warp_m = wid & 1;               // 2 row-strips of 64
    const int warp_n = wid >> 1;              // 4 col-strips of 64

    wmma::fragment<wmma::accumulator, 16, 16, 16, float> acc[4][4];
    #pragma unroll
    for (int mi = 0; mi < 4; mi++)
        #pragma unroll
        for (int ni = 0; ni < 4; ni++) wmma::fill_fragment(acc[mi][ni], 0.0f);

    auto load_chunk = [&](int kc, int st) {
        const int k0 = kc * BK;
        __half* a_base = As + st * A_STAGE;
        __half* b_base = Bs + st * B_STAGE;
        // A: 128 rows x 32 halves = 512 x 16B, 2 per thread
        #pragma unroll
        for (int i = 0; i < 2; i++) {
            int idx = i * 256 + tid;
            int r = idx >> 2, c = idx & 3;
            int gr = m0 + r;
            const __half* src = A + (size_t)(gr < M ? gr : (M - 1)) * DDIM + k0 + c * 8;
            uint32_t dst;
            asm("{ .reg .u64 t; cvta.to.shared.u64 t, %1; cvt.u32.u64 %0, t; }"
                : "=r"(dst) : "l"(a_base + r * LDA + c * 8));
            int sz = (gr < M) ? 16 : 0;
            asm volatile("cp.async.cg.shared.global [%0], [%1], 16, %2;"
                         :: "r"(dst), "l"(src), "r"(sz));
        }
        // B: 32 rows x 256 halves = 1024 x 16B, 4 per thread
        #pragma unroll
        for (int i = 0; i < 4; i++) {
            int idx = i * 256 + tid;
            int r = idx >> 5, c = idx & 31;
            const __half* src = g_Bh + (size_t)(k0 + r) * NCAT + ncol0 + c * 8;
            uint32_t dst;
            asm("{ .reg .u64 t; cvta.to.shared.u64 t, %1; cvt.u32.u64 %0, t; }"
                : "=r"(dst) : "l"(b_base + r * LDB + c * 8));
            asm volatile("cp.async.cg.shared.global [%0], [%1], 16;"
                         :: "r"(dst), "l"(src));
        }
        asm volatile("cp.async.commit_group;" ::: "memory");
    };

    load_chunk(0, 0);
    load_chunk(1, 1);

    #pragma unroll 1
    for (int kc = 0; kc < CHUNKS; kc++) {
        const int st = kc % STAGES;
        if (kc < CHUNKS - 2) {
            asm volatile("cp.async.wait_group 1;" ::: "memory");
        } else {
            asm volatile("cp.async.wait_group 0;" ::: "memory");
        }
        __syncthreads();

        // overwrite the stage of chunk kc-1 (all warps consumed it)
        if (kc + 2 < CHUNKS) load_chunk(kc + 2, (kc + 2) % STAGES);

        const __half* a_base = As + st * A_STAGE;
        const __half* b_base = Bs + st * B_STAGE;

        #pragma unroll
        for (int ks = 0; ks < BK / 16; ks++) {
            wmma::fragment<wmma::matrix_a, 16, 16, 16, __half, wmma::row_major> af[4];
            wmma::fragment<wmma::matrix_b, 16, 16, 16, __half, wmma::row_major> bf[4];
            #pragma unroll
            for (int mi = 0; mi < 4; mi++)
                wmma::load_matrix_sync(af[mi],
                    a_base + (warp_m * 64 + mi * 16) * LDA + ks * 16, LDA);
            #pragma unroll
            for (int ni = 0; ni < 4; ni++)
                wmma::load_matrix_sync(bf[ni],
                    b_base + (ks * 16) * LDB + warp_n * 64 + ni * 16, LDB);
            #pragma unroll
            for (int mi = 0; mi < 4; mi++)
                #pragma unroll
                for (int ni = 0; ni < 4; ni++)
                    wmma::mma_sync(acc[mi][ni], af[mi], bf[ni], acc[mi][ni]);
        }
    }
    __syncthreads();

    const bool is_h = (ncol0 < DDIM);
    const int oc0 = ncol0 & (DDIM - 1);

    if (is_h || m0 + MT > M) {
        // Staged epilogue in two 128x128 halves (fp16 convert for H tiles,
        // guarded fp32 stores for ragged O tiles).
        float* sC = (float*)smem_raw;   // 128x128 f32 = 64KB
        __half* Ht = g_Hh + (size_t)t * slice;
        float* outbase = Obase + t * slice;
        #pragma unroll
        for (int p = 0; p < 2; p++) {
            if ((warp_n >> 1) == p) {
                int lc = (warp_n & 1) * 64;
                #pragma unroll
                for (int mi = 0; mi < 4; mi++)
                    #pragma unroll
                    for (int ni = 0; ni < 4; ni++)
                        wmma::store_matrix_sync(
                            sC + (warp_m * 64 + mi * 16) * 128 + lc + ni * 16,
                            acc[mi][ni], 128, wmma::mem_row_major);
            }
            __syncthreads();
            // drain: 128 rows x 32 float4 per row = 4096 float4
            #pragma unroll
            for (int i = 0; i < 16; i++) {
                int idx = i * 256 + tid;
                int r = idx >> 5, c = idx & 31;   // FIXED: 32 float4 per 128-wide row
                if (m0 + r < M) {
                    float4 v = *(const float4*)(sC + r * 128 + c * 4);
                    int gc = oc0 + p * 128 + c * 4;
                    if (is_h) {
                        half4 h;
                        h.a = __floats2half2_rn(v.x, v.y);
                        h.b = __floats2half2_rn(v.z, v.w);
                        *(half4*)(Ht + (size_t)(m0 + r) * DDIM + gc) = h;
                    } else {
                        *(float4*)(outbase + (size_t)(m0 + r) * DDIM + gc) = v;
                    }
                }
            }
            __syncthreads();
        }
    } else {
        // Full O tile: direct fragment stores to d_out
        float* outbase = Obase + t * slice;
        #pragma unroll
        for (int mi = 0; mi < 4; mi++)
            #pragma unroll
            for (int ni = 0; ni < 4; ni++) {
                int r = m0 + warp_m * 64 + mi * 16;
                int c = oc0 + warp_n * 64 + ni * 16;
                wmma::store_matrix_sync(outbase + (size_t)r * DDIM + c,
                                        acc[mi][ni], DDIM, wmma::mem_row_major);
            }
    }
}

// ---------------------------------------------------------------------------
// Fused gather + self-loop + residual + leaky relu, fp16 H.
// Flat 1D grid ordered t-major so each conv's 51MB H slice stays L2-resident.
// ---------------------------------------------------------------------------
__device__ __forceinline__ void acc_row(const __half* row, int c, float cf,
                                        float& x, float& y, float& z, float& w) {
    half4 v = ((const half4*)row)[c];
    float2 lo = __half22float2(v.a);
    float2 hi = __half22float2(v.b);
    x = fmaf(cf, lo.x, x); y = fmaf(cf, lo.y, y);
    z = fmaf(cf, hi.x, z); w = fmaf(cf, hi.y, w);
}

__global__ __launch_bounds__(128) void gather_finalize_kernel(float* __restrict__ Obase) {
    const int bid = blockIdx.x;
    const int t = bid / NNODES;
    const int n = bid - t * NNODES;
    const int c = threadIdx.x;              // 4-col group index 0..127

    const size_t slice = (size_t)NNODES * DDIM;
    const __half* Ht = g_Hh + t * slice;
    float* O = Obase + t * slice;

    const float dn = g_dis[n];
    const float sc = FILL * dn * dn;

    float ax = 0.f, ay = 0.f, az = 0.f, aw = 0.f;
    float bx = 0.f, by = 0.f, bz = 0.f, bw = 0.f;
    acc_row(Ht + (size_t)n * DDIM, c, sc, ax, ay, az, aw);

    const int beg = g_off[n], end = g_off[n + 1];
    int j = beg;
    for (; j + 1 < end; j += 2) {
        int s0 = g_srcs[j], s1 = g_srcs[j + 1];
        float c0 = g_coef[j], c1 = g_coef[j + 1];
        acc_row(Ht + (size_t)s0 * DDIM, c, c0, ax, ay, az, aw);
        acc_row(Ht + (size_t)s1 * DDIM, c, c1, bx, by, bz, bw);
    }
    if (j < end)
        acc_row(Ht + (size_t)g_srcs[j] * DDIM, c, g_coef[j], ax, ay, az, aw);

    ax += bx; ay += by; az += bz; aw += bw;

    float4* op = (float4*)(O + (size_t)n * DDIM) + c;
    float4 o = *op;
    o.x = o.x + ax; o.x = o.x >= 0.f ? o.x : NEG_SLOPE * o.x;
    o.y = o.y + ay; o.y = o.y >= 0.f ? o.y : NEG_SLOPE * o.y;
    o.z = o.z + az; o.z = o.z >= 0.f ? o.z : NEG_SLOPE * o.z;
    o.w = o.w + aw; o.w = o.w >= 0.f ? o.w : NEG_SLOPE * o.w;
    *op = o;
}

// ---------------------------------------------------------------------------
// Launch (GEMM placed at launch index 3 so ncu's fixed skip captures it)
// ---------------------------------------------------------------------------
extern "C" void kernel_launch(void* const* d_in, const int* in_sizes, int n_in,
                              void* d_out, int out_size)
{
    const float* x0   = (const float*)d_in[0];
    const float* x1   = (const float*)d_in[1];
    const float* x2   = (const float*)d_in[2];
    const int*   adj  = (const int*)d_in[3];
    const float* w    = (const float*)d_in[4];
    const float* Wmat = (const float*)d_in[5];
    const float* Wres = (const float*)d_in[6];
    float* out = (float*)d_out;

    const int* src = adj;
    const int* dst = adj + NEDGES;

    cudaFuncSetAttribute(gemm_fp16_wmma_kernel,
                         cudaFuncAttributeMaxDynamicSharedMemorySize, SMEM_BYTES);

    const size_t slice = (size_t)NNODES * DDIM;
    const int n4 = (int)(slice / 4);

    // 0-1: fp16 conversion of inputs + weights
    dim3 convx_grid((n4 + 255) / 256, 3);
    conv_x_kernel<<<convx_grid, 256>>>(x0, x1, x2, n4);
    conv_b_kernel<<<(DDIM * NCAT + 255) / 256, 256>>>(Wmat, Wres);

    // 2: independent prep
    init_kernel<<<(NNODES + 255) / 256, 256>>>();

    // 3: batched GEMM [H_t | O_t] = X_t @ [W | Wres]
    dim3 gemm_grid(NCAT / NT, (NNODES + MT - 1) / MT, 3);
    gemm_fp16_wmma_kernel<<<gemm_grid, 256, SMEM_BYTES>>>(out, NNODES);

    // 4-9: norm + CSR build (independent of GEMM)
    accum_kernel<<<(NEDGES + 255) / 256, 256>>>(dst, w);
    calc_dis_kernel<<<(NNODES + 255) / 256, 256>>>();
    scan1_kernel<<<SCAN_NB, SCAN_BS>>>();
    scan2_kernel<<<1, 32>>>();
    scan3_kernel<<<(NNODES + 255) / 256, 256>>>();
    fill_kernel<<<(NEDGES + 255) / 256, 256>>>(src, dst, w);

    // 10: batched gather/finalize, t-major for L2 residency of each H slice
    gather_finalize_kernel<<<3 * NNODES, 128>>>(out);
}

// round 13
// speedup vs baseline: 1.0359x; 1.0359x over previous
#include <cuda_runtime.h>
#include <cuda_fp16.h>
#include <mma.h>
#include <cstdint>

using namespace nvcuda;

#define NNODES 50000
#define NEDGES 400000
#define DDIM   512
#define NCAT   1024
#define NEG_SLOPE 0.01f
#define FILL 2.0f

// ---------------------------------------------------------------------------
// Device scratch (static: no allocations allowed)
// ---------------------------------------------------------------------------
__device__ __half g_Bh[(size_t)DDIM * NCAT];        // fp16 [W | Wres] (1MB)
__device__ __half g_Hh[(size_t)3 * NNODES * DDIM];  // H_t = X_t @ W (fp16)
__device__ float  g_deg[NNODES];
__device__ float  g_dis[NNODES];
__device__ int    g_cnt[NNODES];
__device__ int    g_off[NNODES + 1];
__device__ int    g_bsum[128];
__device__ int    g_srcs[NEDGES];
__device__ float  g_coef[NEDGES];

struct alignas(8) half4 { __half2 a, b; };

// ---------------------------------------------------------------------------
// Weight fp16 conversion (1MB, one-shot)
// ---------------------------------------------------------------------------
__global__ void conv_b_kernel(const float* __restrict__ W, const float* __restrict__ Wres) {
    int i = blockIdx.x * blockDim.x + threadIdx.x;
    if (i >= DDIM * NCAT) return;
    int k = i >> 10, n = i & 1023;
    float v = (n < DDIM) ? W[(size_t)k * DDIM + n] : Wres[(size_t)k * DDIM + (n - DDIM)];
    g_Bh[i] = __float2half_rn(v);
}

// ---------------------------------------------------------------------------
// Degree / norm / CSR build
// ---------------------------------------------------------------------------
__global__ void init_kernel() {
    int n = blockIdx.x * blockDim.x + threadIdx.x;
    if (n < NNODES) { g_deg[n] = FILL; g_cnt[n] = 0; }
}
__global__ void accum_kernel(const int* __restrict__ dst, const float* __restrict__ w) {
    int e = blockIdx.x * blockDim.x + threadIdx.x;
    if (e < NEDGES) {
        int d = dst[e];
        atomicAdd(&g_deg[d], w[e]);
        atomicAdd(&g_cnt[d], 1);
    }
}
__global__ void calc_dis_kernel() {
    int n = blockIdx.x * blockDim.x + threadIdx.x;
    if (n < NNODES) {
        float d = g_deg[n];
        g_dis[n] = (d > 0.0f) ? rsqrtf(d) : 0.0f;
    }
}

#define SCAN_BS 512
#define SCAN_NB ((NNODES + SCAN_BS - 1) / SCAN_BS)   // 98

__global__ void scan1_kernel() {
    __shared__ int s[SCAN_BS];
    int tid = threadIdx.x;
    int i = blockIdx.x * SCAN_BS + tid;
    int val = (i < NNODES) ? g_cnt[i] : 0;
    s[tid] = val;
    __syncthreads();
    #pragma unroll
    for (int o = 1; o < SCAN_BS; o <<= 1) {
        int t = (tid >= o) ? s[tid - o] : 0;
        __syncthreads();
        s[tid] += t;
        __syncthreads();
    }
    int incl = s[tid];
    if (i < NNODES) g_off[i] = incl - val;
    if (tid == SCAN_BS - 1) g_bsum[blockIdx.x] = incl;
}
__global__ void scan2_kernel() {
    if (threadIdx.x == 0) {
        int run = 0;
        for (int b = 0; b < SCAN_NB; b++) { int t = g_bsum[b]; g_bsum[b] = run; run += t; }
    }
}
__global__ void scan3_kernel() {
    int i = blockIdx.x * blockDim.x + threadIdx.x;
    if (i < NNODES) { g_off[i] += g_bsum[i >> 9]; g_cnt[i] = 0; }
    if (i == 0) g_off[NNODES] = NEDGES;
}
__global__ void fill_kernel(const int* __restrict__ src, const int* __restrict__ dst,
                            const float* __restrict__ w) {
    int e = blockIdx.x * blockDim.x + threadIdx.x;
    if (e >= NEDGES) return;
    int s = src[e], d = dst[e];
    int pos = atomicAdd(&g_cnt[d], 1);
    int slot = g_off[d] + pos;
    g_srcs[slot] = s;
    g_coef[slot] = g_dis[s] * w[e] * g_dis[d];
}

// ---------------------------------------------------------------------------
// FP16 WMMA GEMM (fp32 accumulate), batched over the 3 inputs via grid.z.
// C_t[M, 1024] = X_t[M,512] @ g_Bh, with A read as fp32 from the original
// inputs and converted to fp16 in-kernel (register-staged, one iteration
// of lookahead) — no separate conv_x pass.
// CTA 128x128, BK=32, 8 warps (32x64 warp tile), 2 CTAs/SM.
// A: 2-stage fp16 smem buffer fed by LDG.128 x4 + cvt + STS (full coverage:
//    256 thr x 4 float4 = 1024 float4 = the whole 128x32 fp32 chunk).
// B: 3-stage cp.async pipeline. One __syncthreads per K-chunk.
// H tiles (cols<512) -> fp16 via smem staging; O tiles -> fp32 direct.
// ---------------------------------------------------------------------------
#define MT 128
#define NT 128
#define BK 32
#define LDA (BK + 8)        // halves; 80B rows
#define LDB (NT + 8)        // halves; 272B rows
#define A_STAGE (MT * LDA)  // 5120 halves (10KB), 2 stages
#define B_STAGE (BK * LDB)  // 4352 halves (8.5KB), 3 stages
#define SMEM_BYTES 65536
#define CHUNKS (DDIM / BK)  // 16

__global__ __launch_bounds__(256, 2) void gemm_fp16_wmma_kernel(
    const float* __restrict__ X0,
    const float* __restrict__ X1,
    const float* __restrict__ X2,
    float* __restrict__ Obase,       // [3, M, 512] (d_out)
    int M)
{
    extern __shared__ char smem_raw[];
    __half* As = (__half*)smem_raw;              // 2 stages
    __half* Bs = As + 2 * A_STAGE;               // 3 stages

    const int tid = threadIdx.x;
    const int wid = tid >> 5;
    const int m0 = blockIdx.y * MT;
    const int ncol0 = blockIdx.x * NT;
    const int t = blockIdx.z;

    const float* A = (t == 0) ? X0 : (t == 1) ? X1 : X2;
    const size_t slice = (size_t)M * DDIM;

    const int warp_m = wid & 3;
    const int warp_n = wid >> 2;

    // A-load geometry: chunk = 128 rows x 8 float4; 2 threads/row, 4 float4 each
    const int a_r = tid >> 1;                    // 0..127
    const int a_c = (tid & 1) * 4;               // float4 index 0 or 4
    const int a_gr = (m0 + a_r < M) ? (m0 + a_r) : (M - 1);
    const float* a_src_base = A + (size_t)a_gr * DDIM;

    wmma::fragment<wmma::accumulator, 16, 16, 16, float> acc[2][4];
    #pragma unroll
    for (int mi = 0; mi < 2; mi++)
        #pragma unroll
        for (int ni = 0; ni < 4; ni++) wmma::fill_fragment(acc[mi][ni], 0.0f);

    float4 areg[4];   // this thread's 4 float4 (16 fp32) of the next A chunk

    auto ldg_a = [&](int kc) {
        const float4* p = (const float4*)(a_src_base + kc * BK) + a_c;
        #pragma unroll
        for (int i = 0; i < 4; i++) areg[i] = __ldg(p + i);
    };
    auto sts_a = [&](int st) {
        __half* a_base = As + st * A_STAGE + a_r * LDA + a_c * 4;
        #pragma unroll
        for (int i = 0; i < 4; i++) {
            half4 h;
            h.a = __floats2half2_rn(areg[i].x, areg[i].y);
            h.b = __floats2half2_rn(areg[i].z, areg[i].w);
            *(half4*)(a_base + i * 4) = h;
        }
    };
    auto load_b = [&](int kc, int st) {
        const int k0 = kc * BK;
        __half* b_base = Bs + st * B_STAGE;
        #pragma unroll
        for (int i = 0; i < 2; i++) {
            int idx = i * 256 + tid;
            int r = idx >> 4, c = idx & 15;
            const __half* src = g_Bh + (size_t)(k0 + r) * NCAT + ncol0 + c * 8;
            uint32_t dst;
            asm("{ .reg .u64 t; cvta.to.shared.u64 t, %1; cvt.u32.u64 %0, t; }"
                : "=r"(dst) : "l"(b_base + r * LDB + c * 8));
            asm volatile("cp.async.cg.shared.global [%0], [%1], 16;"
                         :: "r"(dst), "l"(src));
        }
        asm volatile("cp.async.commit_group;" ::: "memory");
    };

    // prologue: A chunk 0 straight to smem; A chunk 1 into regs; B chunks 0,1
    ldg_a(0); sts_a(0);
    ldg_a(1);
    load_b(0, 0);
    load_b(1, 1);

    #pragma unroll 1
    for (int kc = 0; kc < CHUNKS; kc++) {
        const int stA = kc & 1;
        const int stB = kc % 3;
        if (kc < CHUNKS - 2) {
            asm volatile("cp.async.wait_group 1;" ::: "memory");
        } else {
            asm volatile("cp.async.wait_group 0;" ::: "memory");
        }
        __syncthreads();   // A stage stA & B stage stB ready; prior readers done

        // stage chunk kc+1's A (held in regs), then start fetching kc+2
        if (kc + 1 < CHUNKS) sts_a((kc + 1) & 1);
        if (kc + 2 < CHUNKS) { ldg_a(kc + 2); load_b(kc + 2, (kc + 2) % 3); }

        const __half* a_base = As + stA * A_STAGE;
        const __half* b_base = Bs + stB * B_STAGE;

        #pragma unroll
        for (int ks = 0; ks < BK / 16; ks++) {
            wmma::fragment<wmma::matrix_a, 16, 16, 16, __half, wmma::row_major> af[2];
            wmma::fragment<wmma::matrix_b, 16, 16, 16, __half, wmma::row_major> bf[4];
            #pragma unroll
            for (int mi = 0; mi < 2; mi++)
                wmma::load_matrix_sync(af[mi],
                    a_base + (warp_m * 32 + mi * 16) * LDA + ks * 16, LDA);
            #pragma unroll
            for (int ni = 0; ni < 4; ni++)
                wmma::load_matrix_sync(bf[ni],
                    b_base + (ks * 16) * LDB + warp_n * 64 + ni * 16, LDB);
            #pragma unroll
            for (int mi = 0; mi < 2; mi++)
                #pragma unroll
                for (int ni = 0; ni < 4; ni++)
                    wmma::mma_sync(acc[mi][ni], af[mi], bf[ni], acc[mi][ni]);
        }
    }
    __syncthreads();

    const bool is_h = (ncol0 < DDIM);
    const int oc0 = ncol0 & (DDIM - 1);

    if (is_h) {
        // H tile -> fp16: stage fp32 in smem, convert, write half4 chunks.
        float* sC = (float*)smem_raw;   // 128x128 f32 = 64KB
        #pragma unroll
        for (int mi = 0; mi < 2; mi++)
            #pragma unroll
            for (int ni = 0; ni < 4; ni++) {
                int r = warp_m * 32 + mi * 16;
                int c = warp_n * 64 + ni * 16;
                wmma::store_matrix_sync(sC + r * NT + c, acc[mi][ni], NT,
                                        wmma::mem_row_major);
            }
        __syncthreads();
        __half* Ht = g_Hh + (size_t)t * slice;
        #pragma unroll
        for (int i = 0; i < 16; i++) {
            int idx = i * 256 + tid;
            int r = idx >> 5, c = idx & 31;
            if (m0 + r < M) {
                float4 v = *(const float4*)(sC + r * NT + c * 4);
                half4 h;
                h.a = __floats2half2_rn(v.x, v.y);
                h.b = __floats2half2_rn(v.z, v.w);
                *(half4*)(Ht + (size_t)(m0 + r) * DDIM + oc0 + c * 4) = h;
            }
        }
    } else {
        float* outbase = Obase + t * slice;
        if (m0 + MT <= M) {
            #pragma unroll
            for (int mi = 0; mi < 2; mi++)
                #pragma unroll
                for (int ni = 0; ni < 4; ni++) {
                    int r = m0 + warp_m * 32 + mi * 16;
                    int c = oc0 + warp_n * 64 + ni * 16;
                    wmma::store_matrix_sync(outbase + (size_t)r * DDIM + c,
                                            acc[mi][ni], DDIM, wmma::mem_row_major);
                }
        } else {
            float* sC = (float*)smem_raw;
            #pragma unroll
            for (int mi = 0; mi < 2; mi++)
                #pragma unroll
                for (int ni = 0; ni < 4; ni++) {
                    int r = warp_m * 32 + mi * 16;
                    int c = warp_n * 64 + ni * 16;
                    wmma::store_matrix_sync(sC + r * NT + c, acc[mi][ni], NT,
                                            wmma::mem_row_major);
                }
            __syncthreads();
            #pragma unroll
            for (int i = 0; i < 16; i++) {
                int idx = i * 256 + tid;
                int r = idx >> 5, c = idx & 31;
                if (m0 + r < M) {
                    float4 v = *(const float4*)(sC + r * NT + c * 4);
                    *(float4*)(outbase + (size_t)(m0 + r) * DDIM + oc0 + c * 4) = v;
                }
            }
        }
    }
}

// ---------------------------------------------------------------------------
// Fused gather + self-loop + residual + leaky relu, fp16 H.
// Flat 1D grid ordered t-major so each conv's 51MB H slice stays L2-resident.
// ---------------------------------------------------------------------------
__device__ __forceinline__ void acc_row(const __half* row, int c, float cf,
                                        float& x, float& y, float& z, float& w) {
    half4 v = ((const half4*)row)[c];
    float2 lo = __half22float2(v.a);
    float2 hi = __half22float2(v.b);
    x = fmaf(cf, lo.x, x); y = fmaf(cf, lo.y, y);
    z = fmaf(cf, hi.x, z); w = fmaf(cf, hi.y, w);
}

__global__ __launch_bounds__(128) void gather_finalize_kernel(float* __restrict__ Obase) {
    const int bid = blockIdx.x;
    const int t = bid / NNODES;
    const int n = bid - t * NNODES;
    const int c = threadIdx.x;              // 4-col group index 0..127

    const size_t slice = (size_t)NNODES * DDIM;
    const __half* Ht = g_Hh + t * slice;
    float* O = Obase + t * slice;

    const float dn = g_dis[n];
    const float sc = FILL * dn * dn;

    float ax = 0.f, ay = 0.f, az = 0.f, aw = 0.f;
    float bx = 0.f, by = 0.f, bz = 0.f, bw = 0.f;
    acc_row(Ht + (size_t)n * DDIM, c, sc, ax, ay, az, aw);

    const int beg = g_off[n], end = g_off[n + 1];
    int j = beg;
    for (; j + 1 < end; j += 2) {
        int s0 = g_srcs[j], s1 = g_srcs[j + 1];
        float c0 = g_coef[j], c1 = g_coef[j + 1];
        acc_row(Ht + (size_t)s0 * DDIM, c, c0, ax, ay, az, aw);
        acc_row(Ht + (size_t)s1 * DDIM, c, c1, bx, by, bz, bw);
    }
    if (j < end)
        acc_row(Ht + (size_t)g_srcs[j] * DDIM, c, g_coef[j], ax, ay, az, aw);

    ax += bx; ay += by; az += bz; aw += bw;

    float4* op = (float4*)(O + (size_t)n * DDIM) + c;
    float4 o = *op;
    o.x = o.x + ax; o.x = o.x >= 0.f ? o.x : NEG_SLOPE * o.x;
    o.y = o.y + ay; o.y = o.y >= 0.f ? o.y : NEG_SLOPE * o.y;
    o.z = o.z + az; o.z = o.z >= 0.f ? o.z : NEG_SLOPE * o.z;
    o.w = o.w + aw; o.w = o.w >= 0.f ? o.w : NEG_SLOPE * o.w;
    *op = o;
}

// ---------------------------------------------------------------------------
// Launch (GEMM at launch index 3 so ncu's fixed skip keeps capturing it)
// ---------------------------------------------------------------------------
extern "C" void kernel_launch(void* const* d_in, const int* in_sizes, int n_in,
                              void* d_out, int out_size)
{
    const float* x0   = (const float*)d_in[0];
    const float* x1   = (const float*)d_in[1];
    const float* x2   = (const float*)d_in[2];
    const int*   adj  = (const int*)d_in[3];
    const float* w    = (const float*)d_in[4];
    const float* Wmat = (const float*)d_in[5];
    const float* Wres = (const float*)d_in[6];
    float* out = (float*)d_out;

    const int* src = adj;
    const int* dst = adj + NEDGES;

    cudaFuncSetAttribute(gemm_fp16_wmma_kernel,
                         cudaFuncAttributeMaxDynamicSharedMemorySize, SMEM_BYTES);

    // 0: weights to fp16
    conv_b_kernel<<<(DDIM * NCAT + 255) / 256, 256>>>(Wmat, Wres);
    // 1-2: independent prep
    init_kernel<<<(NNODES + 255) / 256, 256>>>();
    accum_kernel<<<(NEDGES + 255) / 256, 256>>>(dst, w);

    // 3: batched GEMM [H_t | O_t] = X_t @ [W | Wres], fp32 A converted inline
    dim3 gemm_grid(NCAT / NT, (NNODES + MT - 1) / MT, 3);
    gemm_fp16_wmma_kernel<<<gemm_grid, 256, SMEM_BYTES>>>(x0, x1, x2, out, NNODES);

    // 4-8: norm + CSR build
    calc_dis_kernel<<<(NNODES + 255) / 256, 256>>>();
    scan1_kernel<<<SCAN_NB, SCAN_BS>>>();
    scan2_kernel<<<1, 32>>>();
    scan3_kernel<<<(NNODES + 255) / 256, 256>>>();
    fill_kernel<<<(NEDGES + 255) / 256, 256>>>(src, dst, w);

    // 9: batched gather/finalize, t-major for L2 residency of each H slice
    gather_finalize_kernel<<<3 * NNODES, 128>>>(out);
}

// round 15
// speedup vs baseline: 1.1473x; 1.1075x over previous
#include <cuda_runtime.h>
#include <cuda_fp16.h>
#include <mma.h>
#include <cstdint>

using namespace nvcuda;

#define NNODES 50000
#define NEDGES 400000
#define DDIM   512
#define NCAT   1024
#define NEG_SLOPE 0.01f
#define FILL 2.0f

// ---------------------------------------------------------------------------
// Device scratch (static: no allocations allowed)
// ---------------------------------------------------------------------------
__device__ __half g_Bh[(size_t)DDIM * NCAT];        // fp16 [W | Wres] (1MB)
__device__ __half g_Hh[(size_t)3 * NNODES * DDIM];  // H_t = X_t @ W (fp16)
__device__ float  g_deg[NNODES];
__device__ float  g_dis[NNODES];
__device__ int    g_cnt[NNODES];
__device__ int    g_off[NNODES + 1];
__device__ int    g_bsum[128];
__device__ int    g_srcs[NEDGES];
__device__ float  g_coef[NEDGES];

struct alignas(8) half4 { __half2 a, b; };

// ---------------------------------------------------------------------------
// Weight fp16 conversion (1MB, one-shot)
// ---------------------------------------------------------------------------
__global__ void conv_b_kernel(const float* __restrict__ W, const float* __restrict__ Wres) {
    int i = blockIdx.x * blockDim.x + threadIdx.x;
    if (i >= DDIM * NCAT) return;
    int k = i >> 10, n = i & 1023;
    float v = (n < DDIM) ? W[(size_t)k * DDIM + n] : Wres[(size_t)k * DDIM + (n - DDIM)];
    g_Bh[i] = __float2half_rn(v);
}

// ---------------------------------------------------------------------------
// Degree / norm / CSR build
// ---------------------------------------------------------------------------
__global__ void init_kernel() {
    int n = blockIdx.x * blockDim.x + threadIdx.x;
    if (n < NNODES) { g_deg[n] = FILL; g_cnt[n] = 0; }
}
__global__ void accum_kernel(const int* __restrict__ dst, const float* __restrict__ w) {
    int e = blockIdx.x * blockDim.x + threadIdx.x;
    if (e < NEDGES) {
        int d = dst[e];
        atomicAdd(&g_deg[d], w[e]);
        atomicAdd(&g_cnt[d], 1);
    }
}
__global__ void calc_dis_kernel() {
    int n = blockIdx.x * blockDim.x + threadIdx.x;
    if (n < NNODES) {
        float d = g_deg[n];
        g_dis[n] = (d > 0.0f) ? rsqrtf(d) : 0.0f;
    }
}

#define SCAN_BS 512
#define SCAN_NB ((NNODES + SCAN_BS - 1) / SCAN_BS)   // 98

__global__ void scan1_kernel() {
    __shared__ int s[SCAN_BS];
    int tid = threadIdx.x;
    int i = blockIdx.x * SCAN_BS + tid;
    int val = (i < NNODES) ? g_cnt[i] : 0;
    s[tid] = val;
    __syncthreads();
    #pragma unroll
    for (int o = 1; o < SCAN_BS; o <<= 1) {
        int t = (tid >= o) ? s[tid - o] : 0;
        __syncthreads();
        s[tid] += t;
        __syncthreads();
    }
    int incl = s[tid];
    if (i < NNODES) g_off[i] = incl - val;
    if (tid == SCAN_BS - 1) g_bsum[blockIdx.x] = incl;
}
__global__ void scan2_kernel() {
    if (threadIdx.x == 0) {
        int run = 0;
        for (int b = 0; b < SCAN_NB; b++) { int t = g_bsum[b]; g_bsum[b] = run; run += t; }
    }
}
__global__ void scan3_kernel() {
    int i = blockIdx.x * blockDim.x + threadIdx.x;
    if (i < NNODES) { g_off[i] += g_bsum[i >> 9]; g_cnt[i] = 0; }
    if (i == 0) g_off[NNODES] = NEDGES;
}
__global__ void fill_kernel(const int* __restrict__ src, const int* __restrict__ dst,
                            const float* __restrict__ w) {
    int e = blockIdx.x * blockDim.x + threadIdx.x;
    if (e >= NEDGES) return;
    int s = src[e], d = dst[e];
    int pos = atomicAdd(&g_cnt[d], 1);
    int slot = g_off[d] + pos;
    g_srcs[slot] = s;
    g_coef[slot] = g_dis[s] * w[e] * g_dis[d];
}

// ---------------------------------------------------------------------------
// A-resident FP16 WMMA GEMM (fp32 accumulate).
// CTA = 64 rows x full N=1024: A (64x512 fp32) is read from gmem ONCE,
// converted to fp16 into a resident 66.5KB smem buffer, then 4 N-tiles of
// 256 are computed with B streamed via a 3-STAGE cp.async ring (the 2-stage
// version raced: prefetch of kc+2 targeted the stage being read at kc).
// Warp grid 2x4, warp tile 32x64 (2x4 wmma m16n16k16). 2 CTAs/SM.
// H tiles (ncol<512) -> fp16 via 16-row staging in the drained B region;
// O tiles -> fp32 direct fragment stores (staged+guarded on ragged edge).
// ---------------------------------------------------------------------------
#define MT 64
#define NT 256
#define BK 16
#define LDA 520             // halves per A row (1040B)
#define LDB 264             // halves per B chunk row (528B)
#define LDC 260             // f32 staging stride (1040B)
#define A_BYTES (MT * LDA * 2)          // 66560
#define B_STAGE (BK * LDB)              // 4224 halves = 8448 B
#define B_STAGES 3
#define SMEM_BYTES (A_BYTES + B_STAGES * B_STAGE * 2)   // 91904
#define NCHUNK (DDIM / BK)              // 32 per N-tile
#define NITER (NCAT / NT)               // 4

__global__ __launch_bounds__(256, 2) void gemm_fp16_wmma_kernel(
    const float* __restrict__ X0,
    const float* __restrict__ X1,
    const float* __restrict__ X2,
    float* __restrict__ Obase,       // [3, M, 512] (d_out)
    int M)
{
    extern __shared__ char smem_raw[];
    __half* As = (__half*)smem_raw;                 // resident A, 64 x LDA
    __half* Bs = (__half*)(smem_raw + A_BYTES);     // 3 B stages
    float*  sC = (float*)(smem_raw + A_BYTES);      // staging aliases B region

    const int tid = threadIdx.x;
    const int wid = tid >> 5;
    const int m0 = blockIdx.x * MT;
    const int t = blockIdx.y;

    const float* A = (t == 0) ? X0 : (t == 1) ? X1 : X2;
    const size_t slice = (size_t)M * DDIM;

    const int wm = wid & 1;     // 2 row strips of 32
    const int wn = wid >> 1;    // 4 col strips of 64

    // ---- A prologue: 64 rows x 512 fp32 = 8192 float4, 32 per thread ----
    #pragma unroll 8
    for (int i = 0; i < 32; i++) {
        int idx = i * 256 + tid;
        int r = idx >> 7, c4 = idx & 127;     // 128 float4 per row
        int gr = (m0 + r < M) ? (m0 + r) : (M - 1);
        float4 v = __ldg((const float4*)(A + (size_t)gr * DDIM) + c4);
        half4 h;
        h.a = __floats2half2_rn(v.x, v.y);
        h.b = __floats2half2_rn(v.z, v.w);
        *(half4*)(As + r * LDA + c4 * 4) = h;
    }
    __syncthreads();

    auto load_b = [&](int ncol0, int kc, int st) {
        const int k0 = kc * BK;
        __half* b_base = Bs + st * B_STAGE;
        #pragma unroll
        for (int i = 0; i < 2; i++) {
            int idx = i * 256 + tid;
            int r = idx >> 5, c = idx & 31;   // 16 rows x 32 16B-chunks
            const __half* src = g_Bh + (size_t)(k0 + r) * NCAT + ncol0 + c * 8;
            uint32_t dst;
            asm("{ .reg .u64 t; cvta.to.shared.u64 t, %1; cvt.u32.u64 %0, t; }"
                : "=r"(dst) : "l"(b_base + r * LDB + c * 8));
            asm volatile("cp.async.cg.shared.global [%0], [%1], 16;"
                         :: "r"(dst), "l"(src));
        }
        asm volatile("cp.async.commit_group;" ::: "memory");
    };

    #pragma unroll 1
    for (int ni_t = 0; ni_t < NITER; ni_t++) {
        const int ncol0 = ni_t * NT;

        wmma::fragment<wmma::accumulator, 16, 16, 16, float> acc[2][4];
        #pragma unroll
        for (int mi = 0; mi < 2; mi++)
            #pragma unroll
            for (int ni = 0; ni < 4; ni++) wmma::fill_fragment(acc[mi][ni], 0.0f);

        load_b(ncol0, 0, 0);
        load_b(ncol0, 1, 1);

        #pragma unroll 1
        for (int kc = 0; kc < NCHUNK; kc++) {
            const int stB = kc % B_STAGES;
            if (kc < NCHUNK - 2) {
                asm volatile("cp.async.wait_group 1;" ::: "memory");
            } else {
                asm volatile("cp.async.wait_group 0;" ::: "memory");
            }
            __syncthreads();
            // prefetch into (kc+2)%3 != kc%3 (being read) != (kc+1)%3 (in flight)
            if (kc + 2 < NCHUNK) load_b(ncol0, kc + 2, (kc + 2) % B_STAGES);

            const __half* a_base = As + kc * BK;           // k offset in A
            const __half* b_base = Bs + stB * B_STAGE;

            wmma::fragment<wmma::matrix_a, 16, 16, 16, __half, wmma::row_major> af[2];
            wmma::fragment<wmma::matrix_b, 16, 16, 16, __half, wmma::row_major> bf[4];
            #pragma unroll
            for (int mi = 0; mi < 2; mi++)
                wmma::load_matrix_sync(af[mi],
                    a_base + (wm * 32 + mi * 16) * LDA, LDA);
            #pragma unroll
            for (int ni = 0; ni < 4; ni++)
                wmma::load_matrix_sync(bf[ni],
                    b_base + wn * 64 + ni * 16, LDB);
            #pragma unroll
            for (int mi = 0; mi < 2; mi++)
                #pragma unroll
                for (int ni = 0; ni < 4; ni++)
                    wmma::mma_sync(acc[mi][ni], af[mi], bf[ni], acc[mi][ni]);
        }
        __syncthreads();   // B ring drained & all warps done: free for staging

        const bool is_h = (ncol0 < DDIM);
        const int oc0 = ncol0 & (DDIM - 1);

        if (is_h || m0 + MT > M) {
            // Staged: 4 slices of 16 rows through sC (aliases B region)
            __half* Ht = g_Hh + (size_t)t * slice;
            float* outbase = Obase + t * slice;
            #pragma unroll
            for (int s = 0; s < 4; s++) {
                if (wm == (s >> 1)) {
                    int mi = s & 1;
                    #pragma unroll
                    for (int ni = 0; ni < 4; ni++)
                        wmma::store_matrix_sync(sC + wn * 64 + ni * 16,
                                                acc[mi][ni], LDC,
                                                wmma::mem_row_major);
                }
                __syncthreads();
                // drain 16 rows x 64 float4
                #pragma unroll
                for (int i = 0; i < 4; i++) {
                    int idx = i * 256 + tid;
                    int r = idx >> 6, c = idx & 63;
                    int gr = m0 + s * 16 + r;
                    if (gr < M) {
                        float4 v = *(const float4*)(sC + r * LDC + c * 4);
                        if (is_h) {
                            half4 h;
                            h.a = __floats2half2_rn(v.x, v.y);
                            h.b = __floats2half2_rn(v.z, v.w);
                            *(half4*)(Ht + (size_t)gr * DDIM + oc0 + c * 4) = h;
                        } else {
                            *(float4*)(outbase + (size_t)gr * DDIM + oc0 + c * 4) = v;
                        }
                    }
                }
                __syncthreads();
            }
        } else {
            // Full O tile: direct fragment stores to d_out
            float* outbase = Obase + t * slice;
            #pragma unroll
            for (int mi = 0; mi < 2; mi++)
                #pragma unroll
                for (int ni = 0; ni < 4; ni++) {
                    int r = m0 + wm * 32 + mi * 16;
                    int c = oc0 + wn * 64 + ni * 16;
                    wmma::store_matrix_sync(outbase + (size_t)r * DDIM + c,
                                            acc[mi][ni], DDIM, wmma::mem_row_major);
                }
            __syncthreads();   // before next iteration's B prologue
        }
    }
}

// ---------------------------------------------------------------------------
// Fused gather + self-loop + residual + leaky relu, fp16 H.
// Flat 1D grid ordered t-major so each conv's 51MB H slice stays L2-resident.
// ---------------------------------------------------------------------------
__device__ __forceinline__ void acc_row(const __half* row, int c, float cf,
                                        float& x, float& y, float& z, float& w) {
    half4 v = ((const half4*)row)[c];
    float2 lo = __half22float2(v.a);
    float2 hi = __half22float2(v.b);
    x = fmaf(cf, lo.x, x); y = fmaf(cf, lo.y, y);
    z = fmaf(cf, hi.x, z); w = fmaf(cf, hi.y, w);
}

__global__ __launch_bounds__(128) void gather_finalize_kernel(float* __restrict__ Obase) {
    const int bid = blockIdx.x;
    const int t = bid / NNODES;
    const int n = bid - t * NNODES;
    const int c = threadIdx.x;              // 4-col group index 0..127

    const size_t slice = (size_t)NNODES * DDIM;
    const __half* Ht = g_Hh + t * slice;
    float* O = Obase + t * slice;

    const float dn = g_dis[n];
    const float sc = FILL * dn * dn;

    float ax = 0.f, ay = 0.f, az = 0.f, aw = 0.f;
    float bx = 0.f, by = 0.f, bz = 0.f, bw = 0.f;
    acc_row(Ht + (size_t)n * DDIM, c, sc, ax, ay, az, aw);

    const int beg = g_off[n], end = g_off[n + 1];
    int j = beg;
    for (; j + 1 < end; j += 2) {
        int s0 = g_srcs[j], s1 = g_srcs[j + 1];
        float c0 = g_coef[j], c1 = g_coef[j + 1];
        acc_row(Ht + (size_t)s0 * DDIM, c, c0, ax, ay, az, aw);
        acc_row(Ht + (size_t)s1 * DDIM, c, c1, bx, by, bz, bw);
    }
    if (j < end)
        acc_row(Ht + (size_t)g_srcs[j] * DDIM, c, g_coef[j], ax, ay, az, aw);

    ax += bx; ay += by; az += bz; aw += bw;

    float4* op = (float4*)(O + (size_t)n * DDIM) + c;
    float4 o = *op;
    o.x = o.x + ax; o.x = o.x >= 0.f ? o.x : NEG_SLOPE * o.x;
    o.y = o.y + ay; o.y = o.y >= 0.f ? o.y : NEG_SLOPE * o.y;
    o.z = o.z + az; o.z = o.z >= 0.f ? o.z : NEG_SLOPE * o.z;
    o.w = o.w + aw; o.w = o.w >= 0.f ? o.w : NEG_SLOPE * o.w;
    *op = o;
}

// ---------------------------------------------------------------------------
// Launch (GEMM at launch index 3 so ncu's fixed skip keeps capturing it)
// ---------------------------------------------------------------------------
extern "C" void kernel_launch(void* const* d_in, const int* in_sizes, int n_in,
                              void* d_out, int out_size)
{
    const float* x0   = (const float*)d_in[0];
    const float* x1   = (const float*)d_in[1];
    const float* x2   = (const float*)d_in[2];
    const int*   adj  = (const int*)d_in[3];
    const float* w    = (const float*)d_in[4];
    const float* Wmat = (const float*)d_in[5];
    const float* Wres = (const float*)d_in[6];
    float* out = (float*)d_out;

    const int* src = adj;
    const int* dst = adj + NEDGES;

    cudaFuncSetAttribute(gemm_fp16_wmma_kernel,
                         cudaFuncAttributeMaxDynamicSharedMemorySize, SMEM_BYTES);

    // 0: weights to fp16
    conv_b_kernel<<<(DDIM * NCAT + 255) / 256, 256>>>(Wmat, Wres);
    // 1-2: independent prep
    init_kernel<<<(NNODES + 255) / 256, 256>>>();
    accum_kernel<<<(NEDGES + 255) / 256, 256>>>(dst, w);

    // 3: A-resident GEMM, [H_t | O_t] = X_t @ [W | Wres]
    dim3 gemm_grid((NNODES + MT - 1) / MT, 3);   // (782, 3)
    gemm_fp16_wmma_kernel<<<gemm_grid, 256, SMEM_BYTES>>>(x0, x1, x2, out, NNODES);

    // 4-8: norm + CSR build
    calc_dis_kernel<<<(NNODES + 255) / 256, 256>>>();
    scan1_kernel<<<SCAN_NB, SCAN_BS>>>();
    scan2_kernel<<<1, 32>>>();
    scan3_kernel<<<(NNODES + 255) / 256, 256>>>();
    fill_kernel<<<(NEDGES + 255) / 256, 256>>>(src, dst, w);

    // 9: batched gather/finalize, t-major for L2 residency of each H slice
    gather_finalize_kernel<<<3 * NNODES, 128>>>(out);
}

// round 16
// speedup vs baseline: 1.2184x; 1.0620x over previous
#include <cuda_runtime.h>
#include <cuda_fp16.h>
#include <mma.h>
#include <cstdint>

using namespace nvcuda;

#define NNODES 50000
#define NEDGES 400000
#define DDIM   512
#define NCAT   1024
#define NEG_SLOPE 0.01f
#define FILL 2.0f

// ---------------------------------------------------------------------------
// Device scratch (static: no allocations allowed)
// ---------------------------------------------------------------------------
__device__ __half g_Bh[(size_t)DDIM * NCAT];        // fp16 [W | Wres] (1MB)
__device__ __half g_Hh[(size_t)3 * NNODES * DDIM];  // H_t = X_t @ W (fp16)
__device__ float  g_deg[NNODES];
__device__ float  g_dis[NNODES];
__device__ int    g_cnt[NNODES];
__device__ int    g_off[NNODES + 1];
__device__ int    g_bsum[128];
__device__ int    g_srcs[NEDGES];
__device__ float  g_coef[NEDGES];

struct alignas(8) half4 { __half2 a, b; };

// ---------------------------------------------------------------------------
// Weight fp16 conversion (1MB, one-shot)
// ---------------------------------------------------------------------------
__global__ void conv_b_kernel(const float* __restrict__ W, const float* __restrict__ Wres) {
    int i = blockIdx.x * blockDim.x + threadIdx.x;
    if (i >= DDIM * NCAT) return;
    int k = i >> 10, n = i & 1023;
    float v = (n < DDIM) ? W[(size_t)k * DDIM + n] : Wres[(size_t)k * DDIM + (n - DDIM)];
    g_Bh[i] = __float2half_rn(v);
}

// ---------------------------------------------------------------------------
// Degree / norm / CSR build
// ---------------------------------------------------------------------------
__global__ void init_kernel() {
    int n = blockIdx.x * blockDim.x + threadIdx.x;
    if (n < NNODES) { g_deg[n] = FILL; g_cnt[n] = 0; }
}
__global__ void accum_kernel(const int* __restrict__ dst, const float* __restrict__ w) {
    int e = blockIdx.x * blockDim.x + threadIdx.x;
    if (e < NEDGES) {
        int d = dst[e];
        atomicAdd(&g_deg[d], w[e]);
        atomicAdd(&g_cnt[d], 1);
    }
}
__global__ void calc_dis_kernel() {
    int n = blockIdx.x * blockDim.x + threadIdx.x;
    if (n < NNODES) {
        float d = g_deg[n];
        g_dis[n] = (d > 0.0f) ? rsqrtf(d) : 0.0f;
    }
}

#define SCAN_BS 512
#define SCAN_NB ((NNODES + SCAN_BS - 1) / SCAN_BS)   // 98

__global__ void scan1_kernel() {
    __shared__ int s[SCAN_BS];
    int tid = threadIdx.x;
    int i = blockIdx.x * SCAN_BS + tid;
    int val = (i < NNODES) ? g_cnt[i] : 0;
    s[tid] = val;
    __syncthreads();
    #pragma unroll
    for (int o = 1; o < SCAN_BS; o <<= 1) {
        int t = (tid >= o) ? s[tid - o] : 0;
        __syncthreads();
        s[tid] += t;
        __syncthreads();
    }
    int incl = s[tid];
    if (i < NNODES) g_off[i] = incl - val;
    if (tid == SCAN_BS - 1) g_bsum[blockIdx.x] = incl;
}
__global__ void scan2_kernel() {
    if (threadIdx.x == 0) {
        int run = 0;
        for (int b = 0; b < SCAN_NB; b++) { int t = g_bsum[b]; g_bsum[b] = run; run += t; }
    }
}
__global__ void scan3_kernel() {
    int i = blockIdx.x * blockDim.x + threadIdx.x;
    if (i < NNODES) { g_off[i] += g_bsum[i >> 9]; g_cnt[i] = 0; }
    if (i == 0) g_off[NNODES] = NEDGES;
}
__global__ void fill_kernel(const int* __restrict__ src, const int* __restrict__ dst,
                            const float* __restrict__ w) {
    int e = blockIdx.x * blockDim.x + threadIdx.x;
    if (e >= NEDGES) return;
    int s = src[e], d = dst[e];
    int pos = atomicAdd(&g_cnt[d], 1);
    int slot = g_off[d] + pos;
    g_srcs[slot] = s;
    g_coef[slot] = g_dis[s] * w[e] * g_dis[d];
}

// ---------------------------------------------------------------------------
// A-resident FP16 WMMA GEMM (fp32 accumulate).
// CTA = 64 rows x full N=1024: A (64x512 fp32) read from gmem ONCE,
// converted to a resident 66.5KB fp16 smem buffer; 4 N-tiles of 256
// computed with B streamed via a 2-stage, prefetch-distance-1 cp.async
// ring (race-free: iter kc reads stage kc&1, prefetches kc+1 into the
// other stage; the kc+1 barrier orders the next overwrite).
// BK=32: 2 wmma k-steps per barrier -> half the syncs of the BK=16 version.
// Warp grid 2x4, warp tile 32x64. 2 CTAs/SM (smem 100.3KB).
// H tiles (ncol<512) -> fp16 via 16-row staging in the drained B region;
// O tiles -> fp32 direct fragment stores (staged+guarded on ragged edge).
// ---------------------------------------------------------------------------
#define MT 64
#define NT 256
#define BK 32
#define LDA 520             // halves per A row (1040B)
#define LDB 264             // halves per B chunk row (528B)
#define LDC 260             // f32 staging stride (1040B)
#define A_BYTES (MT * LDA * 2)          // 66560
#define B_STAGE (BK * LDB)              // 8448 halves = 16896 B
#define SMEM_BYTES (A_BYTES + 2 * B_STAGE * 2)   // 100352
#define NCHUNK (DDIM / BK)              // 16 per N-tile
#define NITER (NCAT / NT)               // 4

__global__ __launch_bounds__(256, 2) void gemm_fp16_wmma_kernel(
    const float* __restrict__ X0,
    const float* __restrict__ X1,
    const float* __restrict__ X2,
    float* __restrict__ Obase,       // [3, M, 512] (d_out)
    int M)
{
    extern __shared__ char smem_raw[];
    __half* As = (__half*)smem_raw;                 // resident A, 64 x LDA
    __half* Bs = (__half*)(smem_raw + A_BYTES);     // 2 B stages
    float*  sC = (float*)(smem_raw + A_BYTES);      // staging aliases B region

    const int tid = threadIdx.x;
    const int wid = tid >> 5;
    const int m0 = blockIdx.x * MT;
    const int t = blockIdx.y;

    const float* A = (t == 0) ? X0 : (t == 1) ? X1 : X2;
    const size_t slice = (size_t)M * DDIM;

    const int wm = wid & 1;     // 2 row strips of 32
    const int wn = wid >> 1;    // 4 col strips of 64

    // ---- A prologue: 64 rows x 512 fp32 = 8192 float4, 32 per thread ----
    #pragma unroll 8
    for (int i = 0; i < 32; i++) {
        int idx = i * 256 + tid;
        int r = idx >> 7, c4 = idx & 127;     // 128 float4 per row
        int gr = (m0 + r < M) ? (m0 + r) : (M - 1);
        float4 v = __ldg((const float4*)(A + (size_t)gr * DDIM) + c4);
        half4 h;
        h.a = __floats2half2_rn(v.x, v.y);
        h.b = __floats2half2_rn(v.z, v.w);
        *(half4*)(As + r * LDA + c4 * 4) = h;
    }
    __syncthreads();

    auto load_b = [&](int ncol0, int kc, int st) {
        const int k0 = kc * BK;
        __half* b_base = Bs + st * B_STAGE;
        // 32 rows x 32 16B-chunks = 1024, 4 per thread
        #pragma unroll
        for (int i = 0; i < 4; i++) {
            int idx = i * 256 + tid;
            int r = idx >> 5, c = idx & 31;
            const __half* src = g_Bh + (size_t)(k0 + r) * NCAT + ncol0 + c * 8;
            uint32_t dst;
            asm("{ .reg .u64 t; cvta.to.shared.u64 t, %1; cvt.u32.u64 %0, t; }"
                : "=r"(dst) : "l"(b_base + r * LDB + c * 8));
            asm volatile("cp.async.cg.shared.global [%0], [%1], 16;"
                         :: "r"(dst), "l"(src));
        }
        asm volatile("cp.async.commit_group;" ::: "memory");
    };

    #pragma unroll 1
    for (int ni_t = 0; ni_t < NITER; ni_t++) {
        const int ncol0 = ni_t * NT;

        wmma::fragment<wmma::accumulator, 16, 16, 16, float> acc[2][4];
        #pragma unroll
        for (int mi = 0; mi < 2; mi++)
            #pragma unroll
            for (int ni = 0; ni < 4; ni++) wmma::fill_fragment(acc[mi][ni], 0.0f);

        load_b(ncol0, 0, 0);

        #pragma unroll 1
        for (int kc = 0; kc < NCHUNK; kc++) {
            asm volatile("cp.async.wait_group 0;" ::: "memory");  // chunk kc ready
            __syncthreads();   // all warps see it; prior reads of other stage done
            // prefetch next chunk into the OTHER stage (overlaps MMA below)
            if (kc + 1 < NCHUNK) load_b(ncol0, kc + 1, (kc + 1) & 1);

            const __half* a_base = As + kc * BK;           // k offset in A
            const __half* b_base = Bs + (kc & 1) * B_STAGE;

            #pragma unroll
            for (int ks = 0; ks < BK / 16; ks++) {
                wmma::fragment<wmma::matrix_a, 16, 16, 16, __half, wmma::row_major> af[2];
                wmma::fragment<wmma::matrix_b, 16, 16, 16, __half, wmma::row_major> bf[4];
                #pragma unroll
                for (int mi = 0; mi < 2; mi++)
                    wmma::load_matrix_sync(af[mi],
                        a_base + (wm * 32 + mi * 16) * LDA + ks * 16, LDA);
                #pragma unroll
                for (int ni = 0; ni < 4; ni++)
                    wmma::load_matrix_sync(bf[ni],
                        b_base + (ks * 16) * LDB + wn * 64 + ni * 16, LDB);
                #pragma unroll
                for (int mi = 0; mi < 2; mi++)
                    #pragma unroll
                    for (int ni = 0; ni < 4; ni++)
                        wmma::mma_sync(acc[mi][ni], af[mi], bf[ni], acc[mi][ni]);
            }
        }
        __syncthreads();   // B ring drained & all warps done: free for staging

        const bool is_h = (ncol0 < DDIM);
        const int oc0 = ncol0 & (DDIM - 1);

        if (is_h || m0 + MT > M) {
            // Staged: 4 slices of 16 rows through sC (aliases B region)
            __half* Ht = g_Hh + (size_t)t * slice;
            float* outbase = Obase + t * slice;
            #pragma unroll
            for (int s = 0; s < 4; s++) {
                if (wm == (s >> 1)) {
                    int mi = s & 1;
                    #pragma unroll
                    for (int ni = 0; ni < 4; ni++)
                        wmma::store_matrix_sync(sC + wn * 64 + ni * 16,
                                                acc[mi][ni], LDC,
                                                wmma::mem_row_major);
                }
                __syncthreads();
                // drain 16 rows x 64 float4
                #pragma unroll
                for (int i = 0; i < 4; i++) {
                    int idx = i * 256 + tid;
                    int r = idx >> 6, c = idx & 63;
                    int gr = m0 + s * 16 + r;
                    if (gr < M) {
                        float4 v = *(const float4*)(sC + r * LDC + c * 4);
                        if (is_h) {
                            half4 h;
                            h.a = __floats2half2_rn(v.x, v.y);
                            h.b = __floats2half2_rn(v.z, v.w);
                            *(half4*)(Ht + (size_t)gr * DDIM + oc0 + c * 4) = h;
                        } else {
                            *(float4*)(outbase + (size_t)gr * DDIM + oc0 + c * 4) = v;
                        }
                    }
                }
                __syncthreads();
            }
        } else {
            // Full O tile: direct fragment stores to d_out
            float* outbase = Obase + t * slice;
            #pragma unroll
            for (int mi = 0; mi < 2; mi++)
                #pragma unroll
                for (int ni = 0; ni < 4; ni++) {
                    int r = m0 + wm * 32 + mi * 16;
                    int c = oc0 + wn * 64 + ni * 16;
                    wmma::store_matrix_sync(outbase + (size_t)r * DDIM + c,
                                            acc[mi][ni], DDIM, wmma::mem_row_major);
                }
            __syncthreads();   // before next iteration's B prologue
        }
    }
}

// ---------------------------------------------------------------------------
// Fused gather + self-loop + residual + leaky relu, fp16 H.
// Flat 1D grid ordered t-major so each conv's 51MB H slice stays L2-resident.
// ---------------------------------------------------------------------------
__device__ __forceinline__ void acc_row(const __half* row, int c, float cf,
                                        float& x, float& y, float& z, float& w) {
    half4 v = ((const half4*)row)[c];
    float2 lo = __half22float2(v.a);
    float2 hi = __half22float2(v.b);
    x = fmaf(cf, lo.x, x); y = fmaf(cf, lo.y, y);
    z = fmaf(cf, hi.x, z); w = fmaf(cf, hi.y, w);
}

__global__ __launch_bounds__(128) void gather_finalize_kernel(float* __restrict__ Obase) {
    const int bid = blockIdx.x;
    const int t = bid / NNODES;
    const int n = bid - t * NNODES;
    const int c = threadIdx.x;              // 4-col group index 0..127

    const size_t slice = (size_t)NNODES * DDIM;
    const __half* Ht = g_Hh + t * slice;
    float* O = Obase + t * slice;

    const float dn = g_dis[n];
    const float sc = FILL * dn * dn;

    float ax = 0.f, ay = 0.f, az = 0.f, aw = 0.f;
    float bx = 0.f, by = 0.f, bz = 0.f, bw = 0.f;
    acc_row(Ht + (size_t)n * DDIM, c, sc, ax, ay, az, aw);

    const int beg = g_off[n], end = g_off[n + 1];
    int j = beg;
    for (; j + 1 < end; j += 2) {
        int s0 = g_srcs[j], s1 = g_srcs[j + 1];
        float c0 = g_coef[j], c1 = g_coef[j + 1];
        acc_row(Ht + (size_t)s0 * DDIM, c, c0, ax, ay, az, aw);
        acc_row(Ht + (size_t)s1 * DDIM, c, c1, bx, by, bz, bw);
    }
    if (j < end)
        acc_row(Ht + (size_t)g_srcs[j] * DDIM, c, g_coef[j], ax, ay, az, aw);

    ax += bx; ay += by; az += bz; aw += bw;

    float4* op = (float4*)(O + (size_t)n * DDIM) + c;
    float4 o = *op;
    o.x = o.x + ax; o.x = o.x >= 0.f ? o.x : NEG_SLOPE * o.x;
    o.y = o.y + ay; o.y = o.y >= 0.f ? o.y : NEG_SLOPE * o.y;
    o.z = o.z + az; o.z = o.z >= 0.f ? o.z : NEG_SLOPE * o.z;
    o.w = o.w + aw; o.w = o.w >= 0.f ? o.w : NEG_SLOPE * o.w;
    *op = o;
}

// ---------------------------------------------------------------------------
// Launch (GEMM at launch index 3 so ncu's fixed skip keeps capturing it)
// ---------------------------------------------------------------------------
extern "C" void kernel_launch(void* const* d_in, const int* in_sizes, int n_in,
                              void* d_out, int out_size)
{
    const float* x0   = (const float*)d_in[0];
    const float* x1   = (const float*)d_in[1];
    const float* x2   = (const float*)d_in[2];
    const int*   adj  = (const int*)d_in[3];
    const float* w    = (const float*)d_in[4];
    const float* Wmat = (const float*)d_in[5];
    const float* Wres = (const float*)d_in[6];
    float* out = (float*)d_out;

    const int* src = adj;
    const int* dst = adj + NEDGES;

    cudaFuncSetAttribute(gemm_fp16_wmma_kernel,
                         cudaFuncAttributeMaxDynamicSharedMemorySize, SMEM_BYTES);

    // 0: weights to fp16
    conv_b_kernel<<<(DDIM * NCAT + 255) / 256, 256>>>(Wmat, Wres);
    // 1-2: independent prep
    init_kernel<<<(NNODES + 255) / 256, 256>>>();
    accum_kernel<<<(NEDGES + 255) / 256, 256>>>(dst, w);

    // 3: A-resident GEMM, [H_t | O_t] = X_t @ [W | Wres]
    dim3 gemm_grid((NNODES + MT - 1) / MT, 3);   // (782, 3)
    gemm_fp16_wmma_kernel<<<gemm_grid, 256, SMEM_BYTES>>>(x0, x1, x2, out, NNODES);

    // 4-8: norm + CSR build
    calc_dis_kernel<<<(NNODES + 255) / 256, 256>>>();
    scan1_kernel<<<SCAN_NB, SCAN_BS>>>();
    scan2_kernel<<<1, 32>>>();
    scan3_kernel<<<(NNODES + 255) / 256, 256>>>();
    fill_kernel<<<(NEDGES + 255) / 256, 256>>>(src, dst, w);

    // 9: batched gather/finalize, t-major for L2 residency of each H slice
    gather_finalize_kernel<<<3 * NNODES, 128>>>(out);
}